// round 2
// baseline (speedup 1.0000x reference)
#include <cuda_runtime.h>

#define CPB     128   // cells per block
#define THREADS 128
#define MAX_BLOCKS 65536

__device__ float g_partials[MAX_BLOCKS];
__device__ unsigned int g_count = 0;   // self-resetting via atomicInc wrap

__global__ __launch_bounds__(THREADS) void yolo_loss_kernel(
    const float* __restrict__ pred,   // [B*49, 30] contiguous
    const float* __restrict__ targ,   // [B*49, 25] contiguous
    long n_cells,
    float* __restrict__ out)
{
    __shared__ __align__(16) float sP[CPB * 30];  // 15360 B
    __shared__ __align__(16) float sT[CPB * 25];  // 12800 B

    const int tid = threadIdx.x;
    const long cell0 = (long)blockIdx.x * CPB;

    // ---- Stage pred chunk: fully coalesced float4 ----
    {
        long base = cell0 * 30;                      // float index; byte 16-aligned
        int n = (int)min((long)(CPB * 30), n_cells * 30 - base);
        const float4* g4 = reinterpret_cast<const float4*>(pred + base);
        float4* s4 = reinterpret_cast<float4*>(sP);
        int n4 = n >> 2;
        for (int i = tid; i < n4; i += THREADS) s4[i] = g4[i];
        for (int i = (n4 << 2) + tid; i < n; i += THREADS) sP[i] = pred[base + i];
    }
    // ---- Stage targ chunk ----
    {
        long base = cell0 * 25;                      // byte 16-aligned
        int n = (int)min((long)(CPB * 25), n_cells * 25 - base);
        const float4* g4 = reinterpret_cast<const float4*>(targ + base);
        float4* s4 = reinterpret_cast<float4*>(sT);
        int n4 = n >> 2;
        for (int i = tid; i < n4; i += THREADS) s4[i] = g4[i];
        for (int i = (n4 << 2) + tid; i < n; i += THREADS) sT[i] = targ[base + i];
    }
    __syncthreads();

    // ---- Per-cell loss from shared memory ----
    float loss = 0.0f;
    if (cell0 + tid < n_cells) {
        const float* P = sP + tid * 30;
        const float* T = sT + tid * 25;

        float c1 = P[4];
        float c2 = P[9];
        float c  = T[4];
        bool present = (c == 1.0f);
        bool r1 = (c1 > c2);

        if (present) {
            float dobj = (r1 ? c1 : c2) - c;
            loss = dobj * dobj;

            float cls = 0.0f;
            #pragma unroll
            for (int i = 0; i < 20; ++i) {
                float d = P[10 + i] - T[5 + i];
                cls = fmaf(d, d, cls);
            }

            int o = r1 ? 0 : 5;
            float box = 0.0f;
            #pragma unroll
            for (int i = 0; i < 2; ++i) {
                float d = P[o + i] - T[i];
                box = fmaf(d, d, box);
            }
            #pragma unroll
            for (int i = 0; i < 2; ++i) {
                float d = sqrtf(P[o + 2 + i]) - sqrtf(T[2 + i]);
                box = fmaf(d, d, box);
            }
            loss += cls + 5.0f * box;
        } else {
            loss = 0.5f * fmaf(c1, c1, c2 * c2);
        }
    }

    // ---- Block reduction (4 warps) ----
    #pragma unroll
    for (int off = 16; off > 0; off >>= 1)
        loss += __shfl_xor_sync(0xFFFFFFFFu, loss, off);

    __shared__ float wsum[4];
    const int wid = tid >> 5, lid = tid & 31;
    if (lid == 0) wsum[wid] = loss;
    __syncthreads();

    __shared__ int s_last;
    if (tid == 0) {
        float b = wsum[0] + wsum[1] + wsum[2] + wsum[3];
        g_partials[blockIdx.x] = b;
        __threadfence();
        unsigned old = atomicInc(&g_count, gridDim.x - 1);  // wraps to 0 -> replay-safe
        s_last = (old == gridDim.x - 1) ? 1 : 0;
    }
    __syncthreads();

    // ---- Last-arriving block: final reduction, write output ----
    if (s_last) {
        __threadfence();  // acquire: partials written before counter hit max
        double acc = 0.0;
        for (int i = tid; i < (int)gridDim.x; i += THREADS)
            acc += (double)__ldcg(&g_partials[i]);
        #pragma unroll
        for (int off = 16; off > 0; off >>= 1)
            acc += __shfl_xor_sync(0xFFFFFFFFu, acc, off);
        __shared__ double dsum[4];
        if (lid == 0) dsum[wid] = acc;
        __syncthreads();
        if (tid == 0)
            out[0] = (float)(dsum[0] + dsum[1] + dsum[2] + dsum[3]);
    }
}

extern "C" void kernel_launch(void* const* d_in, const int* in_sizes, int n_in,
                              void* d_out, int out_size) {
    const float* pred = (const float*)d_in[0];   // [B, 1470]
    const float* targ = (const float*)d_in[1];   // [B, 1225]
    float* out = (float*)d_out;

    long B = (long)in_sizes[0] / 1470;
    long n_cells = B * 49;
    long blocks = (n_cells + CPB - 1) / CPB;
    if (blocks > MAX_BLOCKS) blocks = MAX_BLOCKS;  // safety (not hit at B=16384)

    yolo_loss_kernel<<<(unsigned)blocks, THREADS>>>(pred, targ, n_cells, out);
}

// round 3
// speedup vs baseline: 1.4755x; 1.4755x over previous
#include <cuda_runtime.h>
#include <cuda_pipeline.h>

#define THREADS 128
#define CPB     96            // cells per chunk
#define PRED_F  (CPB * 30)    // 2880 floats per chunk
#define TARG_F  (CPB * 25)    // 2400 floats per chunk
#define MAX_PART 2048

__device__ float g_partials[MAX_PART];
__device__ unsigned int g_count = 0;   // wraps to 0 each replay via atomicInc

__global__ __launch_bounds__(THREADS) void yolo_loss_kernel(
    const float* __restrict__ pred,   // [B*49, 30]
    const float* __restrict__ targ,   // [B*49, 25]
    long n_cells,
    int n_chunks,
    float* __restrict__ out)
{
    __shared__ __align__(16) float sP[2][PRED_F];  // 2 x 11520 B
    __shared__ __align__(16) float sT[2][TARG_F];  // 2 x  9600 B

    const int tid = threadIdx.x;
    const int grid = gridDim.x;

    // ---- async stage helper (lambda-free, inline) ----
    auto stage = [&](int buf, long chunk) {
        long base_p = chunk * PRED_F;          // byte-16-aligned (11520*chunk)
        long base_t = chunk * TARG_F;          // byte-16-aligned ( 9600*chunk)
        int cells = (int)min((long)CPB, n_cells - chunk * CPB);
        int np4 = (cells * 30) >> 2;           // exact: cells*30 % 4 == 0 for 96/64
        int nt4 = (cells * 25) >> 2;           // exact for 96 (600) and 64 (400)
        const float4* gp = reinterpret_cast<const float4*>(pred + base_p);
        const float4* gt = reinterpret_cast<const float4*>(targ + base_t);
        float4* spp = reinterpret_cast<float4*>(sP[buf]);
        float4* stt = reinterpret_cast<float4*>(sT[buf]);
        for (int i = tid; i < np4; i += THREADS)
            __pipeline_memcpy_async(&spp[i], &gp[i], 16);
        for (int i = tid; i < nt4; i += THREADS)
            __pipeline_memcpy_async(&stt[i], &gt[i], 16);
    };

    float acc = 0.0f;

    long chunk = blockIdx.x;
    int cur = 0;
    if (chunk < n_chunks) stage(cur, chunk);
    __pipeline_commit();

    while (chunk < n_chunks) {
        long next = chunk + grid;
        if (next < n_chunks) stage(cur ^ 1, next);
        __pipeline_commit();
        __pipeline_wait_prior(1);       // current chunk's data is in smem
        __syncthreads();

        // ---- compute current chunk ----
        int cells = (int)min((long)CPB, n_cells - chunk * CPB);
        if (tid < cells) {
            const float* P = sP[cur] + tid * 30;
            const float* T = sT[cur] + tid * 25;

            float c1 = P[4];
            float c2 = P[9];
            float c  = T[4];
            bool present = (c == 1.0f);
            bool r1 = (c1 > c2);

            if (present) {
                float dobj = (r1 ? c1 : c2) - c;
                float loss = dobj * dobj;

                float cls = 0.0f;
                #pragma unroll
                for (int i = 0; i < 20; ++i) {
                    float d = P[10 + i] - T[5 + i];
                    cls = fmaf(d, d, cls);
                }

                int o = r1 ? 0 : 5;
                float box = 0.0f;
                #pragma unroll
                for (int i = 0; i < 2; ++i) {
                    float d = P[o + i] - T[i];
                    box = fmaf(d, d, box);
                }
                #pragma unroll
                for (int i = 0; i < 2; ++i) {
                    float d = sqrtf(P[o + 2 + i]) - sqrtf(T[2 + i]);
                    box = fmaf(d, d, box);
                }
                acc += loss + cls + 5.0f * box;
            } else {
                acc += 0.5f * fmaf(c1, c1, c2 * c2);
            }
        }

        __syncthreads();                // everyone done reading buf before refill
        cur ^= 1;
        chunk = next;
    }

    // ---- block reduction (4 warps) ----
    #pragma unroll
    for (int off = 16; off > 0; off >>= 1)
        acc += __shfl_xor_sync(0xFFFFFFFFu, acc, off);

    __shared__ float wsum[4];
    const int wid = tid >> 5, lid = tid & 31;
    if (lid == 0) wsum[wid] = acc;
    __syncthreads();

    __shared__ int s_last;
    if (tid == 0) {
        g_partials[blockIdx.x] = wsum[0] + wsum[1] + wsum[2] + wsum[3];
        __threadfence();
        unsigned old = atomicInc(&g_count, gridDim.x - 1);
        s_last = (old == gridDim.x - 1) ? 1 : 0;
    }
    __syncthreads();

    // ---- last block: reduce partials, write scalar ----
    if (s_last) {
        __threadfence();
        double d = 0.0;
        for (int i = tid; i < (int)gridDim.x; i += THREADS)
            d += (double)__ldcg(&g_partials[i]);
        #pragma unroll
        for (int off = 16; off > 0; off >>= 1)
            d += __shfl_xor_sync(0xFFFFFFFFu, d, off);
        __shared__ double dsum[4];
        if (lid == 0) dsum[wid] = d;
        __syncthreads();
        if (tid == 0)
            out[0] = (float)(dsum[0] + dsum[1] + dsum[2] + dsum[3]);
    }
}

extern "C" void kernel_launch(void* const* d_in, const int* in_sizes, int n_in,
                              void* d_out, int out_size) {
    const float* pred = (const float*)d_in[0];   // [B, 1470]
    const float* targ = (const float*)d_in[1];   // [B, 1225]
    float* out = (float*)d_out;

    long B = (long)in_sizes[0] / 1470;
    long n_cells = B * 49;
    int n_chunks = (int)((n_cells + CPB - 1) / CPB);

    // persistent grid: 5 blocks/SM (42.2 KB smem each) on 148 SMs
    int blocks = 148 * 5;
    if (blocks > n_chunks) blocks = n_chunks;
    if (blocks > MAX_PART) blocks = MAX_PART;

    yolo_loss_kernel<<<blocks, THREADS>>>(pred, targ, n_cells, n_chunks, out);
}

// round 4
// speedup vs baseline: 1.5501x; 1.0506x over previous
#include <cuda_runtime.h>
#include <cuda_pipeline.h>

#define THREADS 128
#define CPB     128           // cells per chunk (== THREADS)
#define STAGES  4
#define PRED_F  (CPB * 30)    // 3840 floats
#define TARG_F  (CPB * 25)    // 3200 floats
#define MAX_PART 2048

__device__ float g_partials[MAX_PART];
__device__ unsigned int g_count = 0;   // wraps to 0 each replay via atomicInc

__global__ __launch_bounds__(THREADS) void yolo_loss_kernel(
    const float* __restrict__ pred,   // [B*49, 30]
    const float* __restrict__ targ,   // [B*49, 25]
    long n_cells,
    int n_chunks,
    float* __restrict__ out)
{
    // 4 stages x (15360 + 12800) B = 112.6 KB -> 2 blocks/SM
    __shared__ __align__(16) float sP[STAGES][PRED_F];
    __shared__ __align__(16) float sT[STAGES][TARG_F];

    const int tid = threadIdx.x;
    const int grid = gridDim.x;

    auto stage = [&](int slot, long chunk) {
        if (chunk < n_chunks) {
            long base_p = chunk * (long)PRED_F;   // 15360 B * chunk : 16-aligned
            long base_t = chunk * (long)TARG_F;   // 12800 B * chunk : 16-aligned
            int cells = (int)min((long)CPB, n_cells - chunk * CPB);
            int np4 = (cells * 30) >> 2;          // cells*30 % 4 == 0 (128 or tail mult of 2? guard below)
            int nt4 = (cells * 25) >> 2;
            const float4* gp = reinterpret_cast<const float4*>(pred + base_p);
            const float4* gt = reinterpret_cast<const float4*>(targ + base_t);
            float4* spp = reinterpret_cast<float4*>(sP[slot]);
            float4* stt = reinterpret_cast<float4*>(sT[slot]);
            for (int i = tid; i < np4; i += THREADS)
                __pipeline_memcpy_async(&spp[i], &gp[i], 16);
            for (int i = tid; i < nt4; i += THREADS)
                __pipeline_memcpy_async(&stt[i], &gt[i], 16);
            // tail floats not divisible by 4 (only possible on last ragged chunk)
            for (int i = (np4 << 2) + tid; i < cells * 30; i += THREADS)
                __pipeline_memcpy_async(&sP[slot][i], &pred[base_p + i], 4);
            for (int i = (nt4 << 2) + tid; i < cells * 25; i += THREADS)
                __pipeline_memcpy_async(&sT[slot][i], &targ[base_t + i], 4);
        }
        __pipeline_commit();   // always commit to keep group accounting uniform
    };

    // ---- prologue: fill D-1 stages ----
    #pragma unroll
    for (int s = 0; s < STAGES - 1; ++s)
        stage(s, (long)blockIdx.x + (long)s * grid);

    float acc = 0.0f;
    long chunk = blockIdx.x;
    int it = 0;

    while (chunk < n_chunks) {
        __pipeline_wait_prior(STAGES - 2);   // chunk 'it' group complete
        __syncthreads();                     // data visible to all warps

        int slot = it & (STAGES - 1);
        // ---- compute ----
        int cells = (int)min((long)CPB, n_cells - chunk * CPB);
        if (tid < cells) {
            const float* P = sP[slot] + tid * 30;
            const float* T = sT[slot] + tid * 25;

            float c1 = P[4];
            float c2 = P[9];
            float c  = T[4];
            bool present = (c == 1.0f);
            bool r1 = (c1 > c2);

            if (present) {
                float dobj = (r1 ? c1 : c2) - c;
                float loss = dobj * dobj;

                float cls = 0.0f;
                #pragma unroll
                for (int i = 0; i < 20; ++i) {
                    float d = P[10 + i] - T[5 + i];
                    cls = fmaf(d, d, cls);
                }

                int o = r1 ? 0 : 5;
                float box = 0.0f;
                #pragma unroll
                for (int i = 0; i < 2; ++i) {
                    float d = P[o + i] - T[i];
                    box = fmaf(d, d, box);
                }
                #pragma unroll
                for (int i = 0; i < 2; ++i) {
                    float d = sqrtf(P[o + 2 + i]) - sqrtf(T[2 + i]);
                    box = fmaf(d, d, box);
                }
                acc += loss + cls + 5.0f * box;
            } else {
                acc += 0.5f * fmaf(c1, c1, c2 * c2);
            }
        }

        // ---- prefetch chunk it+STAGES-1 into slot (it+STAGES-1)%STAGES ----
        // Safe: that slot held chunk it-1, consumed before this iteration's sync.
        long pf = chunk + (long)(STAGES - 1) * grid;
        stage((it + STAGES - 1) & (STAGES - 1), pf);

        chunk += grid;
        ++it;
    }

    // ---- block reduction (4 warps) ----
    #pragma unroll
    for (int off = 16; off > 0; off >>= 1)
        acc += __shfl_xor_sync(0xFFFFFFFFu, acc, off);

    __shared__ float wsum[4];
    const int wid = tid >> 5, lid = tid & 31;
    if (lid == 0) wsum[wid] = acc;
    __syncthreads();

    __shared__ int s_last;
    if (tid == 0) {
        g_partials[blockIdx.x] = wsum[0] + wsum[1] + wsum[2] + wsum[3];
        __threadfence();
        unsigned old = atomicInc(&g_count, gridDim.x - 1);
        s_last = (old == gridDim.x - 1) ? 1 : 0;
    }
    __syncthreads();

    if (s_last) {
        __threadfence();
        double d = 0.0;
        for (int i = tid; i < (int)gridDim.x; i += THREADS)
            d += (double)__ldcg(&g_partials[i]);
        #pragma unroll
        for (int off = 16; off > 0; off >>= 1)
            d += __shfl_xor_sync(0xFFFFFFFFu, d, off);
        __shared__ double dsum[4];
        if (lid == 0) dsum[wid] = d;
        __syncthreads();
        if (tid == 0)
            out[0] = (float)(dsum[0] + dsum[1] + dsum[2] + dsum[3]);
    }
}

extern "C" void kernel_launch(void* const* d_in, const int* in_sizes, int n_in,
                              void* d_out, int out_size) {
    const float* pred = (const float*)d_in[0];   // [B, 1470]
    const float* targ = (const float*)d_in[1];   // [B, 1225]
    float* out = (float*)d_out;

    long B = (long)in_sizes[0] / 1470;
    long n_cells = B * 49;
    int n_chunks = (int)((n_cells + CPB - 1) / CPB);

    // 2 blocks/SM (112.6 KB smem each) on 148 SMs
    int blocks = 148 * 2;
    if (blocks > n_chunks) blocks = n_chunks;
    if (blocks > MAX_PART) blocks = MAX_PART;

    yolo_loss_kernel<<<blocks, THREADS>>>(pred, targ, n_cells, n_chunks, out);
}